// round 1
// baseline (speedup 1.0000x reference)
#include <cuda_runtime.h>

#define EMBED   1024
#define NHEADS  16
#define HDIM    64
#define NB      4
#define SEQ     2048
#define MTOT    (NB*SEQ)     /* 8192 */
#define KDIM    1024
#define NDIM    1024

// Scratch (device globals; allocation-free per harness rules). 128 MB total.
__device__ float g_Q[(size_t)NB*NHEADS*SEQ*HDIM];  // [b,h,l,d]
__device__ float g_K[(size_t)NB*NHEADS*SEQ*HDIM];
__device__ float g_V[(size_t)NB*NHEADS*SEQ*HDIM];
__device__ float g_O[(size_t)MTOT*EMBED];          // [b*l, e]  e = h*64+d

// ---------------------------------------------------------------------------
// Tiled fp32 SGEMM: C[M,N] = A[M,K] @ W[K,N] + bias
// 128x128 block tile, K-step 8, 256 threads, 8x8 per-thread microtile.
// mode 0/1/2: A = x, store remapped into g_Q/g_K/g_V as [b,h,l,d]
// mode 3:     A = g_O, store plain into Cout
// ---------------------------------------------------------------------------
__global__ void __launch_bounds__(256) sgemm_kernel(
    const float* __restrict__ Ain, const float* __restrict__ W,
    const float* __restrict__ bias, float* __restrict__ Cout, int mode)
{
    __shared__ float As[8][128];
    __shared__ float Bs[8][128];

    const float* A = (mode == 3) ? g_O : Ain;
    float* dst = (mode == 0) ? g_Q : (mode == 1) ? g_K : (mode == 2) ? g_V : Cout;

    int t  = threadIdx.x;
    int tx = t & 15, ty = t >> 4;
    int bm = blockIdx.y * 128;
    int bn = blockIdx.x * 128;

    float acc[8][8];
#pragma unroll
    for (int i = 0; i < 8; i++)
#pragma unroll
        for (int j = 0; j < 8; j++) acc[i][j] = 0.f;

    int arow = t >> 1;            // 0..127
    int acol = (t & 1) * 4;       // 0 or 4
    int brow = t >> 5;            // 0..7
    int bcol = (t & 31) * 4;      // 0..124

    for (int k0 = 0; k0 < KDIM; k0 += 8) {
        float4 av = *(const float4*)&A[(size_t)(bm + arow) * KDIM + k0 + acol];
        As[acol+0][arow] = av.x;
        As[acol+1][arow] = av.y;
        As[acol+2][arow] = av.z;
        As[acol+3][arow] = av.w;
        float4 bv = *(const float4*)&W[(size_t)(k0 + brow) * NDIM + bn + bcol];
        *(float4*)&Bs[brow][bcol] = bv;
        __syncthreads();
#pragma unroll
        for (int kk = 0; kk < 8; kk++) {
            float a[8], b[8];
            *(float4*)&a[0] = *(float4*)&As[kk][ty*8];
            *(float4*)&a[4] = *(float4*)&As[kk][ty*8+4];
            *(float4*)&b[0] = *(float4*)&Bs[kk][tx*8];
            *(float4*)&b[4] = *(float4*)&Bs[kk][tx*8+4];
#pragma unroll
            for (int i = 0; i < 8; i++)
#pragma unroll
                for (int j = 0; j < 8; j++)
                    acc[i][j] += a[i] * b[j];
        }
        __syncthreads();
    }

#pragma unroll
    for (int i = 0; i < 8; i++) {
        int m = bm + ty*8 + i;
#pragma unroll
        for (int j = 0; j < 8; j++) {
            int n = bn + tx*8 + j;
            float v = acc[i][j] + bias[n];
            if (mode <= 2) {
                int b_ = m >> 11, l = m & (SEQ-1);
                int h  = n >> 6,  d = n & 63;
                dst[((((size_t)b_*NHEADS + h)*SEQ) + l)*HDIM + d] = v;
            } else {
                dst[(size_t)m * NDIM + n] = v;
            }
        }
    }
}

// ---------------------------------------------------------------------------
// Flash attention: one CTA per (b,h, 64-row q tile). 256 threads.
// Thread (rg,cg): rg=t/16 owns q-rows rg*4..+3, cg=t%16 owns 4 k-cols / 4 o-dims.
// Online softmax with finite -1e30 init (matches reference semantics exactly,
// including uniform output on fully-masked rows).
// ---------------------------------------------------------------------------
#define ATT_SMEM_FLOATS (64*64 + 3*64*65)

__global__ void __launch_bounds__(256) attn_kernel(const int* __restrict__ mask)
{
    extern __shared__ float sm[];
    float* Qs = sm;                // [64][64]
    float* Ks = Qs + 64*64;        // [64][65]
    float* Vs = Ks + 64*65;        // [64][65]
    float* Ps = Vs + 64*65;        // [64][65]

    int t  = threadIdx.x;
    int bh = blockIdx.y;
    int b  = bh >> 4;
    int h  = bh & 15;
    int qbase = blockIdx.x * 64;

    const float* Qp = g_Q + (size_t)bh * SEQ * HDIM + (size_t)qbase * HDIM;
    const float* Kp = g_K + (size_t)bh * SEQ * HDIM;
    const float* Vp = g_V + (size_t)bh * SEQ * HDIM;
    const int* mrow = mask + (size_t)b * SEQ * SEQ;

    int rg = t >> 4, cg = t & 15;
    int r0 = rg * 4, c0 = cg * 4;

    for (int f = t; f < 1024; f += 256)
        ((float4*)Qs)[f] = ((const float4*)Qp)[f];

    float m_i[4], l_i[4], acc[4][4];
#pragma unroll
    for (int i = 0; i < 4; i++) {
        m_i[i] = -1e30f; l_i[i] = 0.f;
#pragma unroll
        for (int j = 0; j < 4; j++) acc[i][j] = 0.f;
    }
    __syncthreads();

    for (int kt = 0; kt < SEQ/64; kt++) {
        int kbase = kt * 64;
        const float4* kg = (const float4*)(Kp + (size_t)kbase * HDIM);
        const float4* vg = (const float4*)(Vp + (size_t)kbase * HDIM);
        for (int f = t; f < 1024; f += 256) {
            int row = f >> 4, col = (f & 15) * 4;
            float4 kv = kg[f];
            float4 vv = vg[f];
            float* kd = &Ks[row*65 + col];
            kd[0]=kv.x; kd[1]=kv.y; kd[2]=kv.z; kd[3]=kv.w;
            float* vd = &Vs[row*65 + col];
            vd[0]=vv.x; vd[1]=vv.y; vd[2]=vv.z; vd[3]=vv.w;
        }
        __syncthreads();

        // S = Q @ K^T  (4x4 per thread)
        float s[4][4];
#pragma unroll
        for (int i = 0; i < 4; i++)
#pragma unroll
            for (int j = 0; j < 4; j++) s[i][j] = 0.f;

#pragma unroll 4
        for (int d = 0; d < 64; d++) {
            float qv[4], kv[4];
#pragma unroll
            for (int i = 0; i < 4; i++) qv[i] = Qs[(r0+i)*64 + d];
#pragma unroll
            for (int j = 0; j < 4; j++) kv[j] = Ks[(c0+j)*65 + d];
#pragma unroll
            for (int i = 0; i < 4; i++)
#pragma unroll
                for (int j = 0; j < 4; j++)
                    s[i][j] += qv[i] * kv[j];
        }

        // mask, scale, online softmax update
#pragma unroll
        for (int i = 0; i < 4; i++) {
            const int4 mk = *(const int4*)&mrow[(size_t)(qbase+r0+i)*SEQ + kbase + c0];
            float sv[4];
            sv[0] = ((mk.x == 0) ? -1e20f : s[i][0]) * 0.125f;
            sv[1] = ((mk.y == 0) ? -1e20f : s[i][1]) * 0.125f;
            sv[2] = ((mk.z == 0) ? -1e20f : s[i][2]) * 0.125f;
            sv[3] = ((mk.w == 0) ? -1e20f : s[i][3]) * 0.125f;

            float mx = fmaxf(fmaxf(sv[0], sv[1]), fmaxf(sv[2], sv[3]));
            mx = fmaxf(mx, __shfl_xor_sync(0xffffffffu, mx, 8));
            mx = fmaxf(mx, __shfl_xor_sync(0xffffffffu, mx, 4));
            mx = fmaxf(mx, __shfl_xor_sync(0xffffffffu, mx, 2));
            mx = fmaxf(mx, __shfl_xor_sync(0xffffffffu, mx, 1));

            float nm = fmaxf(m_i[i], mx);
            float corr = __expf(m_i[i] - nm);

            float p0 = __expf(sv[0] - nm);
            float p1 = __expf(sv[1] - nm);
            float p2 = __expf(sv[2] - nm);
            float p3 = __expf(sv[3] - nm);
            float* pr = &Ps[(r0+i)*65 + c0];
            pr[0] = p0; pr[1] = p1; pr[2] = p2; pr[3] = p3;

            float ls = p0 + p1 + p2 + p3;
            ls += __shfl_xor_sync(0xffffffffu, ls, 8);
            ls += __shfl_xor_sync(0xffffffffu, ls, 4);
            ls += __shfl_xor_sync(0xffffffffu, ls, 2);
            ls += __shfl_xor_sync(0xffffffffu, ls, 1);

            l_i[i] = l_i[i] * corr + ls;
            m_i[i] = nm;
#pragma unroll
            for (int j = 0; j < 4; j++) acc[i][j] *= corr;
        }
        __syncthreads();

        // O += P @ V  (4 rows x 4 dims per thread; dims c0..c0+3)
#pragma unroll 4
        for (int k = 0; k < 64; k++) {
            float pv[4], vv[4];
#pragma unroll
            for (int i = 0; i < 4; i++) pv[i] = Ps[(r0+i)*65 + k];
#pragma unroll
            for (int j = 0; j < 4; j++) vv[j] = Vs[k*65 + c0 + j];
#pragma unroll
            for (int i = 0; i < 4; i++)
#pragma unroll
                for (int j = 0; j < 4; j++)
                    acc[i][j] += pv[i] * vv[j];
        }
        __syncthreads();
    }

#pragma unroll
    for (int i = 0; i < 4; i++) {
        float inv = 1.f / l_i[i];
        int q = qbase + r0 + i;
        float* op = &g_O[(size_t)(b*SEQ + q)*EMBED + h*HDIM + c0];
#pragma unroll
        for (int j = 0; j < 4; j++) op[j] = acc[i][j] * inv;
    }
}

// ---------------------------------------------------------------------------
extern "C" void kernel_launch(void* const* d_in, const int* in_sizes, int n_in,
                              void* d_out, int out_size)
{
    const float* x    = (const float*)d_in[0];
    const int*   mask = (const int*)  d_in[1];
    const float* Wq   = (const float*)d_in[2];
    const float* bq   = (const float*)d_in[3];
    const float* Wk   = (const float*)d_in[4];
    const float* bk   = (const float*)d_in[5];
    const float* Wv   = (const float*)d_in[6];
    const float* bv   = (const float*)d_in[7];
    const float* Wo   = (const float*)d_in[8];
    const float* bo   = (const float*)d_in[9];

    dim3 gg(NDIM/128, MTOT/128);       // (8, 64)
    sgemm_kernel<<<gg, 256>>>(x, Wq, bq, nullptr, 0);
    sgemm_kernel<<<gg, 256>>>(x, Wk, bk, nullptr, 1);
    sgemm_kernel<<<gg, 256>>>(x, Wv, bv, nullptr, 2);

    int smem = ATT_SMEM_FLOATS * (int)sizeof(float);   // ~66 KB
    cudaFuncSetAttribute(attn_kernel, cudaFuncAttributeMaxDynamicSharedMemorySize, smem);
    dim3 ga(SEQ/64, NB*NHEADS);        // (32, 64)
    attn_kernel<<<ga, 256, smem>>>(mask);

    sgemm_kernel<<<gg, 256>>>(nullptr, Wo, bo, (float*)d_out, 3);
}

// round 3
// speedup vs baseline: 1.5885x; 1.5885x over previous
#include <cuda_runtime.h>
#include <cuda_bf16.h>
#include <cstdint>

#define EMBED   1024
#define NHEADS  16
#define HDIM    64
#define NB      4
#define SEQ     2048
#define MTOT    (NB*SEQ)     /* 8192 */
#define KDIM    1024
#define NDIM    1024

// ---------------------------------------------------------------------------
// Scratch (device globals; allocation-free per harness rules).
// ---------------------------------------------------------------------------
__device__ float g_Q[(size_t)NB*NHEADS*SEQ*HDIM];  // [b,h,l,d] fp32
__device__ float g_K[(size_t)NB*NHEADS*SEQ*HDIM];
__device__ float g_V[(size_t)NB*NHEADS*SEQ*HDIM];
__device__ float g_O[(size_t)MTOT*EMBED];          // [b*l, e]

__device__ __nv_bfloat16 g_xhi[(size_t)MTOT*KDIM]; // split x
__device__ __nv_bfloat16 g_xlo[(size_t)MTOT*KDIM];
__device__ __nv_bfloat16 g_ohi[(size_t)MTOT*KDIM]; // split attention output
__device__ __nv_bfloat16 g_olo[(size_t)MTOT*KDIM];
__device__ __nv_bfloat16 g_wthi[(size_t)4*NDIM*KDIM]; // W^T split, [N][K], 4 mats
__device__ __nv_bfloat16 g_wtlo[(size_t)4*NDIM*KDIM];

// ---------------------------------------------------------------------------
// mma.sync helpers (arch-portable PTX; runs on tensor pipe, OK at compute_103)
// ---------------------------------------------------------------------------
__device__ __forceinline__ uint32_t smem_u32(const void* p) {
    uint32_t a;
    asm("{ .reg .u64 t; cvta.to.shared.u64 t, %1; cvt.u32.u64 %0, t; }"
        : "=r"(a) : "l"(p));
    return a;
}

__device__ __forceinline__ void ldsm_x4(uint32_t* r, uint32_t addr) {
    asm volatile("ldmatrix.sync.aligned.m8n8.x4.shared.b16 {%0,%1,%2,%3}, [%4];"
        : "=r"(r[0]), "=r"(r[1]), "=r"(r[2]), "=r"(r[3]) : "r"(addr));
}

__device__ __forceinline__ void mma_bf16(float* c, const uint32_t* a, const uint32_t* b) {
    asm volatile(
        "mma.sync.aligned.m16n8k16.row.col.f32.bf16.bf16.f32 "
        "{%0,%1,%2,%3}, {%4,%5,%6,%7}, {%8,%9}, {%0,%1,%2,%3};"
        : "+f"(c[0]), "+f"(c[1]), "+f"(c[2]), "+f"(c[3])
        : "r"(a[0]), "r"(a[1]), "r"(a[2]), "r"(a[3]), "r"(b[0]), "r"(b[1]));
}

// ---------------------------------------------------------------------------
// Split fp32 -> (bf16 hi, bf16 lo). n4 = count of float4 elements.
// ---------------------------------------------------------------------------
__global__ void __launch_bounds__(256) split_kernel(
    const float* __restrict__ in, __nv_bfloat16* __restrict__ hi,
    __nv_bfloat16* __restrict__ lo, int n4)
{
    int i = blockIdx.x * 256 + threadIdx.x;
    if (i >= n4) return;
    float4 v = ((const float4*)in)[i];
    __nv_bfloat16 h0 = __float2bfloat16(v.x);
    __nv_bfloat16 h1 = __float2bfloat16(v.y);
    __nv_bfloat16 h2 = __float2bfloat16(v.z);
    __nv_bfloat16 h3 = __float2bfloat16(v.w);
    __nv_bfloat16 l0 = __float2bfloat16(v.x - __bfloat162float(h0));
    __nv_bfloat16 l1 = __float2bfloat16(v.y - __bfloat162float(h1));
    __nv_bfloat16 l2 = __float2bfloat16(v.z - __bfloat162float(h2));
    __nv_bfloat16 l3 = __float2bfloat16(v.w - __bfloat162float(h3));
    __nv_bfloat162* hi2 = (__nv_bfloat162*)hi;
    __nv_bfloat162* lo2 = (__nv_bfloat162*)lo;
    hi2[2*i]   = __nv_bfloat162(h0, h1);
    hi2[2*i+1] = __nv_bfloat162(h2, h3);
    lo2[2*i]   = __nv_bfloat162(l0, l1);
    lo2[2*i+1] = __nv_bfloat162(l2, l3);
}

// ---------------------------------------------------------------------------
// Transpose + split: W[K][N] fp32 -> Wt_hi/Wt_lo [N][K] bf16.
// ---------------------------------------------------------------------------
__global__ void __launch_bounds__(256) wsplit_kernel(
    const float* __restrict__ W, __nv_bfloat16* __restrict__ hi,
    __nv_bfloat16* __restrict__ lo)
{
    __shared__ float tile[32][33];
    int tx = threadIdx.x & 31, ty0 = threadIdx.x >> 5;
    int bn = blockIdx.x * 32;   // N
    int bk = blockIdx.y * 32;   // K
#pragma unroll
    for (int i = 0; i < 4; i++) {
        int ty = ty0 + i * 8;
        tile[ty][tx] = W[(size_t)(bk + ty) * NDIM + bn + tx];
    }
    __syncthreads();
#pragma unroll
    for (int i = 0; i < 4; i++) {
        int ty = ty0 + i * 8;
        float v = tile[tx][ty];   // = W[bk+tx][bn+ty]
        __nv_bfloat16 h = __float2bfloat16(v);
        size_t o = (size_t)(bn + ty) * KDIM + bk + tx;
        hi[o] = h;
        lo[o] = __float2bfloat16(v - __bfloat162float(h));
    }
}

// ---------------------------------------------------------------------------
// mma.sync split-bf16 GEMM:
//   C[128x128 tile] = A[M,K] @ Bt[N,K]^T (+bias), fp32 accum in registers.
//   3 MMAs per operand pair per k16 (hi*hi + hi*lo + lo*hi).
// 256 threads = 8 warps in 2(M)x4(N) grid, warp tile 64x32.
// K-chunk 32, double-buffered smem (LDG->regs overlapped with compute).
// Smem rows padded to 80B -> conflict-free ldmatrix.
// mode 0/1/2: remap store into g_Q/g_K/g_V [b,h,l,d]; mode 3: plain to Cout.
// ---------------------------------------------------------------------------
#define ROWB      80                  /* padded row bytes (32 bf16 -> 80B) */
#define MAT_BYTES (128*ROWB)          /* 10240 */
#define STG_BYTES (4*MAT_BYTES)       /* 40960 */
#define GEMM_SMEM (2*STG_BYTES)       /* 81920 */
#define OFF_AHI   0
#define OFF_ALO   MAT_BYTES
#define OFF_BHI   (2*MAT_BYTES)
#define OFF_BLO   (3*MAT_BYTES)

__global__ void __launch_bounds__(256, 1) gemm_mma(
    const __nv_bfloat16* __restrict__ Ahi, const __nv_bfloat16* __restrict__ Alo,
    const __nv_bfloat16* __restrict__ Bhi, const __nv_bfloat16* __restrict__ Blo,
    const float* __restrict__ bias, float* __restrict__ Cout, int mode)
{
    extern __shared__ char sm[];
    const uint32_t sb = smem_u32(sm);
    const int t = threadIdx.x;
    const int lane = t & 31;
    const int wid = t >> 5;
    const int wm = wid >> 2;          // 0..1
    const int wn = wid & 3;           // 0..3
    const int bm = blockIdx.y * 128;
    const int bn = blockIdx.x * 128;

    // staging indices (each thread: 2 uint4 per matrix per stage)
    const int r0s = t >> 2,            seg0 = t & 3;
    const int r1s = (t + 256) >> 2,    seg1 = (t + 256) & 3;

    // ldmatrix lane addressing
    const int a_row  = lane & 15;
    const int a_half = lane >> 4;
    const int b_row  = ((lane >> 4) << 3) + (lane & 7);
    const int b_half = (lane >> 3) & 1;

    float acc[16][4];
#pragma unroll
    for (int i = 0; i < 16; i++)
#pragma unroll
        for (int j = 0; j < 4; j++) acc[i][j] = 0.f;

    const size_t a0g = (size_t)(bm + r0s) * KDIM + seg0 * 8;
    const size_t a1g = (size_t)(bm + r1s) * KDIM + seg1 * 8;
    const size_t b0g = (size_t)(bn + r0s) * KDIM + seg0 * 8;
    const size_t b1g = (size_t)(bn + r1s) * KDIM + seg1 * 8;
    const uint32_t s0 = (uint32_t)(r0s * ROWB + seg0 * 16);
    const uint32_t s1 = (uint32_t)(r1s * ROWB + seg1 * 16);

    // prologue: stage 0
    {
        uint4 vah0 = *(const uint4*)(Ahi + a0g);
        uint4 vah1 = *(const uint4*)(Ahi + a1g);
        uint4 val0 = *(const uint4*)(Alo + a0g);
        uint4 val1 = *(const uint4*)(Alo + a1g);
        uint4 vbh0 = *(const uint4*)(Bhi + b0g);
        uint4 vbh1 = *(const uint4*)(Bhi + b1g);
        uint4 vbl0 = *(const uint4*)(Blo + b0g);
        uint4 vbl1 = *(const uint4*)(Blo + b1g);
        *(uint4*)(sm + OFF_AHI + s0) = vah0;
        *(uint4*)(sm + OFF_AHI + s1) = vah1;
        *(uint4*)(sm + OFF_ALO + s0) = val0;
        *(uint4*)(sm + OFF_ALO + s1) = val1;
        *(uint4*)(sm + OFF_BHI + s0) = vbh0;
        *(uint4*)(sm + OFF_BHI + s1) = vbh1;
        *(uint4*)(sm + OFF_BLO + s0) = vbl0;
        *(uint4*)(sm + OFF_BLO + s1) = vbl1;
    }
    __syncthreads();

    const int NSTG = KDIM / 32;       // 32
    for (int s = 0; s < NSTG; s++) {
        // issue next-stage global loads
        uint4 vah0, vah1, val0, val1, vbh0, vbh1, vbl0, vbl1;
        if (s + 1 < NSTG) {
            int k0 = (s + 1) * 32;
            vah0 = *(const uint4*)(Ahi + a0g + k0);
            vah1 = *(const uint4*)(Ahi + a1g + k0);
            val0 = *(const uint4*)(Alo + a0g + k0);
            val1 = *(const uint4*)(Alo + a1g + k0);
            vbh0 = *(const uint4*)(Bhi + b0g + k0);
            vbh1 = *(const uint4*)(Bhi + b1g + k0);
            vbl0 = *(const uint4*)(Blo + b0g + k0);
            vbl1 = *(const uint4*)(Blo + b1g + k0);
        }

        // compute current stage
        const uint32_t stg = sb + (uint32_t)((s & 1) * STG_BYTES);
        const uint32_t aAhi = stg + OFF_AHI + (uint32_t)((wm * 64 + a_row) * ROWB + a_half * 16);
        const uint32_t aAlo = aAhi + MAT_BYTES;
        const uint32_t aBhi = stg + OFF_BHI + (uint32_t)((wn * 32 + b_row) * ROWB + b_half * 16);
        const uint32_t aBlo = aBhi + MAT_BYTES;

#pragma unroll
        for (int kk = 0; kk < 2; kk++) {
            uint32_t ah[4][4], al[4][4], bh[2][4], bl[2][4];
            const uint32_t koff = (uint32_t)(kk * 32);
#pragma unroll
            for (int mt = 0; mt < 4; mt++) {
                ldsm_x4(ah[mt], aAhi + mt * (16 * ROWB) + koff);
                ldsm_x4(al[mt], aAlo + mt * (16 * ROWB) + koff);
            }
#pragma unroll
            for (int nt = 0; nt < 2; nt++) {
                ldsm_x4(bh[nt], aBhi + nt * (16 * ROWB) + koff);
                ldsm_x4(bl[nt], aBlo + nt * (16 * ROWB) + koff);
            }
#pragma unroll
            for (int mt = 0; mt < 4; mt++) {
#pragma unroll
                for (int j = 0; j < 4; j++) {
                    const uint32_t* bhf = &bh[j >> 1][(j & 1) * 2];
                    const uint32_t* blf = &bl[j >> 1][(j & 1) * 2];
                    float* c = acc[mt * 4 + j];
                    mma_bf16(c, ah[mt], bhf);
                    mma_bf16(c, ah[mt], blf);
                    mma_bf16(c, al[mt], bhf);
                }
            }
        }

        // store next stage and sync
        if (s + 1 < NSTG) {
            char* dst = sm + ((s + 1) & 1) * STG_BYTES;
            *(uint4*)(dst + OFF_AHI + s0) = vah0;
            *(uint4*)(dst + OFF_AHI + s1) = vah1;
            *(uint4*)(dst + OFF_ALO + s0) = val0;
            *(uint4*)(dst + OFF_ALO + s1) = val1;
            *(uint4*)(dst + OFF_BHI + s0) = vbh0;
            *(uint4*)(dst + OFF_BHI + s1) = vbh1;
            *(uint4*)(dst + OFF_BLO + s0) = vbl0;
            *(uint4*)(dst + OFF_BLO + s1) = vbl1;
            __syncthreads();
        }
    }

    // epilogue
    float* dst = (mode == 0) ? g_Q : (mode == 1) ? g_K : (mode == 2) ? g_V : Cout;
    const int g = lane >> 2;
    const int cq = (lane & 3) * 2;
#pragma unroll
    for (int mt = 0; mt < 4; mt++) {
#pragma unroll
        for (int j = 0; j < 4; j++) {
            const float* c = acc[mt * 4 + j];
            int row = bm + wm * 64 + mt * 16 + g;
            int col = bn + wn * 32 + j * 8 + cq;
            float b0 = bias[col], b1 = bias[col + 1];
#pragma unroll
            for (int half = 0; half < 2; half++) {
                int r = row + half * 8;
                float2 v = make_float2(c[half * 2 + 0] + b0, c[half * 2 + 1] + b1);
                if (mode <= 2) {
                    int b_ = r >> 11, l = r & (SEQ - 1);
                    int h = col >> 6, d = col & 63;
                    *(float2*)&dst[((((size_t)b_ * NHEADS + h) * SEQ) + l) * HDIM + d] = v;
                } else {
                    *(float2*)&dst[(size_t)r * NDIM + col] = v;
                }
            }
        }
    }
}

// ---------------------------------------------------------------------------
// Flash attention (fp32 SIMT, unchanged — round-4 target)
// ---------------------------------------------------------------------------
#define ATT_SMEM_FLOATS (64*64 + 3*64*65)

__global__ void __launch_bounds__(256) attn_kernel(const int* __restrict__ mask)
{
    extern __shared__ float smf[];
    float* Qs = smf;               // [64][64]
    float* Ks = Qs + 64*64;        // [64][65]
    float* Vs = Ks + 64*65;        // [64][65]
    float* Ps = Vs + 64*65;        // [64][65]

    int t  = threadIdx.x;
    int bh = blockIdx.y;
    int b  = bh >> 4;
    int qbase = blockIdx.x * 64;

    const float* Qp = g_Q + (size_t)bh * SEQ * HDIM + (size_t)qbase * HDIM;
    const float* Kp = g_K + (size_t)bh * SEQ * HDIM;
    const float* Vp = g_V + (size_t)bh * SEQ * HDIM;
    const int* mrow = mask + (size_t)b * SEQ * SEQ;
    int h = bh & 15;

    int rg = t >> 4, cg = t & 15;
    int r0 = rg * 4, c0 = cg * 4;

    for (int f = t; f < 1024; f += 256)
        ((float4*)Qs)[f] = ((const float4*)Qp)[f];

    float m_i[4], l_i[4], acc[4][4];
#pragma unroll
    for (int i = 0; i < 4; i++) {
        m_i[i] = -1e30f; l_i[i] = 0.f;
#pragma unroll
        for (int j = 0; j < 4; j++) acc[i][j] = 0.f;
    }
    __syncthreads();

    for (int kt = 0; kt < SEQ/64; kt++) {
        int kbase = kt * 64;
        const float4* kg = (const float4*)(Kp + (size_t)kbase * HDIM);
        const float4* vg = (const float4*)(Vp + (size_t)kbase * HDIM);
        for (int f = t; f < 1024; f += 256) {
            int row = f >> 4, col = (f & 15) * 4;
            float4 kv = kg[f];
            float4 vv = vg[f];
            float* kd = &Ks[row*65 + col];
            kd[0]=kv.x; kd[1]=kv.y; kd[2]=kv.z; kd[3]=kv.w;
            float* vd = &Vs[row*65 + col];
            vd[0]=vv.x; vd[1]=vv.y; vd[2]=vv.z; vd[3]=vv.w;
        }
        __syncthreads();

        float s[4][4];
#pragma unroll
        for (int i = 0; i < 4; i++)
#pragma unroll
            for (int j = 0; j < 4; j++) s[i][j] = 0.f;

#pragma unroll 4
        for (int d = 0; d < 64; d++) {
            float qv[4], kv[4];
#pragma unroll
            for (int i = 0; i < 4; i++) qv[i] = Qs[(r0+i)*64 + d];
#pragma unroll
            for (int j = 0; j < 4; j++) kv[j] = Ks[(c0+j)*65 + d];
#pragma unroll
            for (int i = 0; i < 4; i++)
#pragma unroll
                for (int j = 0; j < 4; j++)
                    s[i][j] += qv[i] * kv[j];
        }

#pragma unroll
        for (int i = 0; i < 4; i++) {
            const int4 mk = *(const int4*)&mrow[(size_t)(qbase+r0+i)*SEQ + kbase + c0];
            float sv[4];
            sv[0] = ((mk.x == 0) ? -1e20f : s[i][0]) * 0.125f;
            sv[1] = ((mk.y == 0) ? -1e20f : s[i][1]) * 0.125f;
            sv[2] = ((mk.z == 0) ? -1e20f : s[i][2]) * 0.125f;
            sv[3] = ((mk.w == 0) ? -1e20f : s[i][3]) * 0.125f;

            float mx = fmaxf(fmaxf(sv[0], sv[1]), fmaxf(sv[2], sv[3]));
            mx = fmaxf(mx, __shfl_xor_sync(0xffffffffu, mx, 8));
            mx = fmaxf(mx, __shfl_xor_sync(0xffffffffu, mx, 4));
            mx = fmaxf(mx, __shfl_xor_sync(0xffffffffu, mx, 2));
            mx = fmaxf(mx, __shfl_xor_sync(0xffffffffu, mx, 1));

            float nm = fmaxf(m_i[i], mx);
            float corr = __expf(m_i[i] - nm);

            float p0 = __expf(sv[0] - nm);
            float p1 = __expf(sv[1] - nm);
            float p2 = __expf(sv[2] - nm);
            float p3 = __expf(sv[3] - nm);
            float* pr = &Ps[(r0+i)*65 + c0];
            pr[0] = p0; pr[1] = p1; pr[2] = p2; pr[3] = p3;

            float ls = p0 + p1 + p2 + p3;
            ls += __shfl_xor_sync(0xffffffffu, ls, 8);
            ls += __shfl_xor_sync(0xffffffffu, ls, 4);
            ls += __shfl_xor_sync(0xffffffffu, ls, 2);
            ls += __shfl_xor_sync(0xffffffffu, ls, 1);

            l_i[i] = l_i[i] * corr + ls;
            m_i[i] = nm;
#pragma unroll
            for (int j = 0; j < 4; j++) acc[i][j] *= corr;
        }
        __syncthreads();

#pragma unroll 4
        for (int k = 0; k < 64; k++) {
            float pv[4], vv[4];
#pragma unroll
            for (int i = 0; i < 4; i++) pv[i] = Ps[(r0+i)*65 + k];
#pragma unroll
            for (int j = 0; j < 4; j++) vv[j] = Vs[k*65 + c0 + j];
#pragma unroll
            for (int i = 0; i < 4; i++)
#pragma unroll
                for (int j = 0; j < 4; j++)
                    acc[i][j] += pv[i] * vv[j];
        }
        __syncthreads();
    }

#pragma unroll
    for (int i = 0; i < 4; i++) {
        float inv = 1.f / l_i[i];
        int q = qbase + r0 + i;
        float* op = &g_O[(size_t)(b*SEQ + q)*EMBED + h*HDIM + c0];
#pragma unroll
        for (int j = 0; j < 4; j++) op[j] = acc[i][j] * inv;
    }
}

// ---------------------------------------------------------------------------
extern "C" void kernel_launch(void* const* d_in, const int* in_sizes, int n_in,
                              void* d_out, int out_size)
{
    const float* x    = (const float*)d_in[0];
    const int*   mask = (const int*)  d_in[1];
    const float* Wq   = (const float*)d_in[2];
    const float* bq   = (const float*)d_in[3];
    const float* Wk   = (const float*)d_in[4];
    const float* bk   = (const float*)d_in[5];
    const float* Wv   = (const float*)d_in[6];
    const float* bv   = (const float*)d_in[7];
    const float* Wo   = (const float*)d_in[8];
    const float* bo   = (const float*)d_in[9];

    // Resolve device-global scratch addresses
    __nv_bfloat16 *xhi, *xlo, *ohi, *olo, *wthi, *wtlo;
    float *oO;
    cudaGetSymbolAddress((void**)&xhi,  g_xhi);
    cudaGetSymbolAddress((void**)&xlo,  g_xlo);
    cudaGetSymbolAddress((void**)&ohi,  g_ohi);
    cudaGetSymbolAddress((void**)&olo,  g_olo);
    cudaGetSymbolAddress((void**)&wthi, g_wthi);
    cudaGetSymbolAddress((void**)&wtlo, g_wtlo);
    cudaGetSymbolAddress((void**)&oO,   g_O);

    const size_t WSZ = (size_t)NDIM * KDIM;

    // Split x into bf16 hi/lo
    int n4x = MTOT * KDIM / 4;
    split_kernel<<<(n4x + 255) / 256, 256>>>(x, xhi, xlo, n4x);

    // Transpose+split all four weight matrices
    dim3 wg(NDIM / 32, KDIM / 32);
    wsplit_kernel<<<wg, 256>>>(Wq, wthi + 0 * WSZ, wtlo + 0 * WSZ);
    wsplit_kernel<<<wg, 256>>>(Wk, wthi + 1 * WSZ, wtlo + 1 * WSZ);
    wsplit_kernel<<<wg, 256>>>(Wv, wthi + 2 * WSZ, wtlo + 2 * WSZ);
    wsplit_kernel<<<wg, 256>>>(Wo, wthi + 3 * WSZ, wtlo + 3 * WSZ);

    cudaFuncSetAttribute(gemm_mma, cudaFuncAttributeMaxDynamicSharedMemorySize, GEMM_SMEM);
    dim3 gg(NDIM / 128, MTOT / 128);   // (8, 64)

    gemm_mma<<<gg, 256, GEMM_SMEM>>>(xhi, xlo, wthi + 0 * WSZ, wtlo + 0 * WSZ, bq, nullptr, 0);
    gemm_mma<<<gg, 256, GEMM_SMEM>>>(xhi, xlo, wthi + 1 * WSZ, wtlo + 1 * WSZ, bk, nullptr, 1);
    gemm_mma<<<gg, 256, GEMM_SMEM>>>(xhi, xlo, wthi + 2 * WSZ, wtlo + 2 * WSZ, bv, nullptr, 2);

    int smem = ATT_SMEM_FLOATS * (int)sizeof(float);
    cudaFuncSetAttribute(attn_kernel, cudaFuncAttributeMaxDynamicSharedMemorySize, smem);
    dim3 ga(SEQ / 64, NB * NHEADS);    // (32, 64)
    attn_kernel<<<ga, 256, smem>>>(mask);

    // Split attention output, final projection
    split_kernel<<<(n4x + 255) / 256, 256>>>(oO, ohi, olo, n4x);
    gemm_mma<<<gg, 256, GEMM_SMEM>>>(ohi, olo, wthi + 3 * WSZ, wtlo + 3 * WSZ, bo, (float*)d_out, 3);
}